// round 9
// baseline (speedup 1.0000x reference)
#include <cuda_runtime.h>
#include <cuda_fp16.h>
#include <cstdint>

#define PB 64
#define PS 4096
#define PD 256
#define PL 16

#define TM 128
#define TN 256
#define KC 64
#define NCHUNK (PD / KC)   // 4
#define THREADS 512

// per-stage tiles: A 128 rows x 128B, B 256 rows x 128B (fp16)
#define A_SZ (128 * 128)                 // 16384
#define B_SZ (256 * 128)                 // 32768
#define STAGE (A_SZ + B_SZ)              // 49152
#define SMEM_BYTES (2 * STAGE)           // 98304

// Pre-converted, pre-swizzled fp16 W: [lang][chunk][row][64 halfs (swizzled 16B units)]
__device__ __align__(16) __half W16g[PL * PD * PD];

__device__ __forceinline__ uint32_t smem_u32(const void* p) {
    uint32_t a;
    asm("{ .reg .u64 t; cvta.to.shared.u64 t, %1; cvt.u32.u64 %0, t; }"
        : "=r"(a) : "l"(p));
    return a;
}

#define LDSM4(R0, R1, R2, R3, A)                                             \
    asm volatile("ldmatrix.sync.aligned.m8n8.x4.shared.b16 {%0,%1,%2,%3}, [%4];" \
                 : "=r"(R0), "=r"(R1), "=r"(R2), "=r"(R3) : "r"(A))

__device__ __forceinline__ void mma_f16(float* d, const uint32_t* a,
                                        const uint32_t* b) {
    asm volatile(
        "mma.sync.aligned.m16n8k16.row.col.f32.f16.f16.f32 "
        "{%0,%1,%2,%3}, {%4,%5,%6,%7}, {%8,%9}, {%0,%1,%2,%3};"
        : "+f"(d[0]), "+f"(d[1]), "+f"(d[2]), "+f"(d[3])
        : "r"(a[0]), "r"(a[1]), "r"(a[2]), "r"(a[3]), "r"(b[0]), "r"(b[1]));
}

__device__ __forceinline__ void sts64(uint32_t addr, uint32_t a, uint32_t b) {
    asm volatile("st.shared.v2.b32 [%0], {%1, %2};" :: "r"(addr), "r"(a), "r"(b));
}

__device__ __forceinline__ void cpa16(uint32_t dst, const void* gsrc) {
    asm volatile("cp.async.cg.shared.global [%0], [%1], 16;"
                 :: "r"(dst), "l"(gsrc));
}
#define CP_COMMIT() asm volatile("cp.async.commit_group;" ::: "memory")
#define CP_WAIT0()  asm volatile("cp.async.wait_group 0;" ::: "memory")

// swizzled byte offset for (row, 16B-chunk c) in a 128B-row tile
__device__ __forceinline__ uint32_t swz(int row, int c) {
    return (uint32_t)(row * 128 + (((c ^ (row & 7)) << 4)));
}

__device__ __forceinline__ uint32_t cvt2(float a, float b) {
    __half2 h = __floats2half2_rn(a, b);
    return *reinterpret_cast<uint32_t*>(&h);
}

// ---------------- pre-pass: W fp32 -> fp16, pre-swizzled tile layout ----------------
__global__ void cvtW_kernel(const float* __restrict__ W) {
    int idx = blockIdx.x * 256 + threadIdx.x;     // 0 .. 131071 (16B groups)
    int lang = idx >> 13;
    int rem = idx & 8191;
    int chunk = rem >> 11;
    int rem2 = rem & 2047;
    int r = rem2 >> 3;
    int g = rem2 & 7;
    const float* src = W + (((size_t)lang * PD + r) * PD + chunk * KC + g * 8);
    float4 v0 = ((const float4*)src)[0];
    float4 v1 = ((const float4*)src)[1];
    uint4 o;
    o.x = cvt2(v0.x, v0.y);
    o.y = cvt2(v0.z, v0.w);
    o.z = cvt2(v1.x, v1.y);
    o.w = cvt2(v1.z, v1.w);
    int gs = g ^ (r & 7);
    *(uint4*)(W16g + (size_t)lang * 65536 + chunk * 16384 + r * 64 + gs * 8) = o;
}

// ---------------- main GEMM ----------------
__global__ __launch_bounds__(THREADS, 1)
void mm_f16b_kernel(const float* __restrict__ X,
                    const int* __restrict__ pid,
                    float* __restrict__ out) {
    extern __shared__ char smem[];
    const int b  = blockIdx.z;
    const int s0 = blockIdx.x * TM;
    const int tid = threadIdx.x;
    const int wid = tid >> 5;
    const int lid = tid & 31;

    int lang = pid[b];
    const float* __restrict__ Xb = X   + ((size_t)b * PS + s0) * PD;
    float* __restrict__       Ob = out + ((size_t)b * PS + s0) * PD;

    // ---------------- passthrough ----------------
    if (lang < 0) {
        #pragma unroll 8
        for (int i = 0; i < 16; ++i) {
            int idx = i * THREADS + tid;     // 8192 float4 in 128x256 tile
            ((float4*)Ob)[idx] = ((const float4*)Xb)[idx];
        }
        return;
    }
    if (lang >= PL) lang = PL - 1;
    const __half* __restrict__ Wl = W16g + (size_t)lang * 65536;

    const uint32_t sb = smem_u32(smem);

    // warp layout: 2 (M) x 8 (N); warp tile 64 x 32
    const int m0 = (wid & 1) * 64;
    const int n0 = (wid >> 1) * 32;

    // A staging: each thread owns 4 float4 of the chunk
    const int ar  = tid >> 2;            // row 0..127
    const int ak0 = (tid & 3) * 16;      // k offset 0/16/32/48

    float acc[4][4][4];
    #pragma unroll
    for (int f = 0; f < 4; ++f)
        #pragma unroll
        for (int g = 0; g < 4; ++g)
            #pragma unroll
            for (int q = 0; q < 4; ++q) acc[f][g][q] = 0.f;

    // ---- B: async copy one chunk (pre-swizzled fp16) ----
    auto issueB = [&](int ch, int stg) {
        const uint32_t swb = sb + stg * STAGE + A_SZ;
        const __half* src = Wl + ch * 16384;
        #pragma unroll
        for (int i = 0; i < 4; ++i) {
            int idx = i * THREADS + tid;      // 2048 x 16B = 32 KB
            cpa16(swb + idx * 16, src + idx * 8);
        }
        CP_COMMIT();
    };

    // ---- A: load fp32 into regs (no stall: no consumer until storeA) ----
    auto loadA = [&](int kb, float4* v) {
        const float* p = Xb + (size_t)ar * PD + kb + ak0;
        v[0] = ((const float4*)p)[0];
        v[1] = ((const float4*)p)[1];
        v[2] = ((const float4*)p)[2];
        v[3] = ((const float4*)p)[3];
    };
    // ---- A: convert + store swizzled ----
    auto storeA = [&](const float4* v, int stg) {
        const uint32_t sa = sb + stg * STAGE;
        #pragma unroll
        for (int i = 0; i < 4; ++i) {
            int k4 = ak0 + i * 4;
            uint32_t off = swz(ar, k4 >> 3) + ((k4 & 7) << 1);
            sts64(sa + off, cvt2(v[i].x, v[i].y), cvt2(v[i].z, v[i].w));
        }
    };

    // ---- consume one stage: 4 k16 steps ----
    auto consume = [&](int stg) {
        const uint32_t sa = sb + stg * STAGE;
        const uint32_t sw = sa + A_SZ;
        #pragma unroll
        for (int ks = 0; ks < 4; ++ks) {
            uint32_t ah[4][4];
            #pragma unroll
            for (int f = 0; f < 4; ++f) {
                int r = m0 + f * 16 + (lid & 15);
                int c = ks * 2 + (lid >> 4);
                LDSM4(ah[f][0], ah[f][1], ah[f][2], ah[f][3], sa + swz(r, c));
            }
            uint32_t bh[4][2];
            #pragma unroll
            for (int g2 = 0; g2 < 2; ++g2) {
                int r = n0 + g2 * 16 + (lid & 7) + ((lid >> 4) << 3);
                int c = ks * 2 + ((lid >> 3) & 1);
                LDSM4(bh[2 * g2][0], bh[2 * g2][1],
                      bh[2 * g2 + 1][0], bh[2 * g2 + 1][1], sw + swz(r, c));
            }
            #pragma unroll
            for (int f = 0; f < 4; ++f)
                #pragma unroll
                for (int g = 0; g < 4; ++g)
                    mma_f16(acc[f][g], ah[f], bh[g]);
        }
    };

    // prologue
    float4 v[4];
    issueB(0, 0);
    loadA(0, v);
    storeA(v, 0);
    CP_WAIT0();
    __syncthreads();

    #pragma unroll
    for (int c = 0; c < NCHUNK; ++c) {
        if (c + 1 < NCHUNK) {
            issueB(c + 1, (c + 1) & 1);       // async
            loadA((c + 1) * KC, v);           // LDGs issued, not consumed yet
        }
        consume(c & 1);                        // MMA hides the A-load latency
        if (c + 1 < NCHUNK) {
            storeA(v, (c + 1) & 1);            // loads complete by now
            CP_WAIT0();
            __syncthreads();
        }
    }

    // ---------------- epilogue ----------------
    const int tr = lid >> 2;          // 0..7
    const int tc = (lid & 3) * 2;     // 0,2,4,6
    #pragma unroll
    for (int f = 0; f < 4; ++f) {
        #pragma unroll
        for (int g = 0; g < 4; ++g) {
            int row = m0 + f * 16 + tr;
            int col = n0 + g * 8 + tc;
            float* p0 = Ob + (size_t)row * PD + col;
            *(float2*)p0            = make_float2(acc[f][g][0], acc[f][g][1]);
            *(float2*)(p0 + 8 * PD) = make_float2(acc[f][g][2], acc[f][g][3]);
        }
    }
}

extern "C" void kernel_launch(void* const* d_in, const int* in_sizes, int n_in,
                              void* d_out, int out_size) {
    const float* X    = (const float*)d_in[0];   // right_emb (B,S,D) f32
    const float* Wmap = (const float*)d_in[1];   // mapping (L,D,D) f32
    const int*   pid  = (const int*)d_in[2];     // pair_id (B,1) i32

    cvtW_kernel<<<512, 256>>>(Wmap);

    cudaFuncSetAttribute(mm_f16b_kernel,
                         cudaFuncAttributeMaxDynamicSharedMemorySize, SMEM_BYTES);
    dim3 grid(PS / TM, 1, PB);   // (32, 1, 64) = 2048 CTAs
    mm_f16b_kernel<<<grid, THREADS, SMEM_BYTES>>>(X, pid, (float*)d_out);
}

// round 10
// speedup vs baseline: 1.0166x; 1.0166x over previous
#include <cuda_runtime.h>
#include <cuda_fp16.h>
#include <cstdint>

#define PB 64
#define PS 4096
#define PD 256
#define PL 16

#define TM 128
#define TN 256
#define KC 64
#define NCHUNK (PD / KC)   // 4
#define THREADS 512

#define A32_SZ (128 * KC * 4)            // 32768  fp32 staging
#define A16_SZ (128 * 128)               // 16384  fp16 tile (128B rows)
#define B_SZ   (256 * 128)               // 32768  fp16 tile
// layout: A32[2] | A16[2] | B16[3]
#define OFF_A32 0
#define OFF_A16 (2 * A32_SZ)
#define OFF_B16 (OFF_A16 + 2 * A16_SZ)
#define SMEM_BYTES (OFF_B16 + 3 * B_SZ)  // 196608 = 192 KB

// Pre-converted, pre-swizzled fp16 W: [lang][chunk][row][64 halfs (swizzled 16B units)]
__device__ __align__(16) __half W16g[PL * PD * PD];

__device__ __forceinline__ uint32_t smem_u32(const void* p) {
    uint32_t a;
    asm("{ .reg .u64 t; cvta.to.shared.u64 t, %1; cvt.u32.u64 %0, t; }"
        : "=r"(a) : "l"(p));
    return a;
}

#define LDSM4(R0, R1, R2, R3, A)                                             \
    asm volatile("ldmatrix.sync.aligned.m8n8.x4.shared.b16 {%0,%1,%2,%3}, [%4];" \
                 : "=r"(R0), "=r"(R1), "=r"(R2), "=r"(R3) : "r"(A))

__device__ __forceinline__ void mma_f16(float* d, const uint32_t* a,
                                        const uint32_t* b) {
    asm volatile(
        "mma.sync.aligned.m16n8k16.row.col.f32.f16.f16.f32 "
        "{%0,%1,%2,%3}, {%4,%5,%6,%7}, {%8,%9}, {%0,%1,%2,%3};"
        : "+f"(d[0]), "+f"(d[1]), "+f"(d[2]), "+f"(d[3])
        : "r"(a[0]), "r"(a[1]), "r"(a[2]), "r"(a[3]), "r"(b[0]), "r"(b[1]));
}

__device__ __forceinline__ void sts64(uint32_t addr, uint32_t a, uint32_t b) {
    asm volatile("st.shared.v2.b32 [%0], {%1, %2};" :: "r"(addr), "r"(a), "r"(b));
}

__device__ __forceinline__ void lds128(uint32_t addr, float4& v) {
    asm volatile("ld.shared.v4.f32 {%0,%1,%2,%3}, [%4];"
                 : "=f"(v.x), "=f"(v.y), "=f"(v.z), "=f"(v.w) : "r"(addr));
}

__device__ __forceinline__ void cpa16(uint32_t dst, const void* gsrc) {
    asm volatile("cp.async.cg.shared.global [%0], [%1], 16;"
                 :: "r"(dst), "l"(gsrc));
}
#define CP_COMMIT() asm volatile("cp.async.commit_group;" ::: "memory")
#define CP_WAIT(N)  asm volatile("cp.async.wait_group %0;" :: "n"(N) : "memory")

// swizzled byte offset for (row, 16B-chunk c) in a 128B-row tile
__device__ __forceinline__ uint32_t swz(int row, int c) {
    return (uint32_t)(row * 128 + (((c ^ (row & 7)) << 4)));
}

__device__ __forceinline__ uint32_t cvt2(float a, float b) {
    __half2 h = __floats2half2_rn(a, b);
    return *reinterpret_cast<uint32_t*>(&h);
}

// ---------------- pre-pass: W fp32 -> fp16, pre-swizzled tile layout ----------------
__global__ void cvtW_kernel(const float* __restrict__ W) {
    int idx = blockIdx.x * 256 + threadIdx.x;     // 0 .. 131071 (16B groups)
    int lang = idx >> 13;
    int rem = idx & 8191;
    int chunk = rem >> 11;
    int rem2 = rem & 2047;
    int r = rem2 >> 3;
    int g = rem2 & 7;
    const float* src = W + (((size_t)lang * PD + r) * PD + chunk * KC + g * 8);
    float4 v0 = ((const float4*)src)[0];
    float4 v1 = ((const float4*)src)[1];
    uint4 o;
    o.x = cvt2(v0.x, v0.y);
    o.y = cvt2(v0.z, v0.w);
    o.z = cvt2(v1.x, v1.y);
    o.w = cvt2(v1.z, v1.w);
    int gs = g ^ (r & 7);
    *(uint4*)(W16g + (size_t)lang * 65536 + chunk * 16384 + r * 64 + gs * 8) = o;
}

// ---------------- main GEMM ----------------
__global__ __launch_bounds__(THREADS, 1)
void mm_f16p_kernel(const float* __restrict__ X,
                    const int* __restrict__ pid,
                    float* __restrict__ out) {
    extern __shared__ char smem[];
    const int b  = blockIdx.z;
    const int s0 = blockIdx.x * TM;
    const int tid = threadIdx.x;
    const int wid = tid >> 5;
    const int lid = tid & 31;

    int lang = pid[b];
    const float* __restrict__ Xb = X   + ((size_t)b * PS + s0) * PD;
    float* __restrict__       Ob = out + ((size_t)b * PS + s0) * PD;

    // ---------------- passthrough ----------------
    if (lang < 0) {
        #pragma unroll 8
        for (int i = 0; i < 16; ++i) {
            int idx = i * THREADS + tid;     // 8192 float4 in 128x256 tile
            ((float4*)Ob)[idx] = ((const float4*)Xb)[idx];
        }
        return;
    }
    if (lang >= PL) lang = PL - 1;
    const __half* __restrict__ Wl = W16g + (size_t)lang * 65536;

    const uint32_t sb   = smem_u32(smem);
    const uint32_t sA32 = sb + OFF_A32;
    const uint32_t sA16 = sb + OFF_A16;
    const uint32_t sB16 = sb + OFF_B16;

    // warp layout: 2 (M) x 8 (N); warp tile 64 x 32
    const int m0 = (wid & 1) * 64;
    const int n0 = (wid >> 1) * 32;

    float acc[4][4][4];
    #pragma unroll
    for (int f = 0; f < 4; ++f)
        #pragma unroll
        for (int g = 0; g < 4; ++g)
            #pragma unroll
            for (int q = 0; q < 4; ++q) acc[f][g][q] = 0.f;

    // ---- issue one chunk: A fp32 (raw) + B fp16 (pre-swizzled), all async ----
    auto issue = [&](int ch) {
        const uint32_t a32 = sA32 + (ch & 1) * A32_SZ;
        #pragma unroll
        for (int i = 0; i < 4; ++i) {
            int idx = i * THREADS + tid;      // 2048 x 16B = 32 KB (A chunk fp32)
            int r  = idx >> 4;
            int k4 = (idx & 15) * 4;
            cpa16(a32 + idx * 16, Xb + (size_t)r * PD + ch * KC + k4);
        }
        const uint32_t b16 = sB16 + (ch % 3) * B_SZ;
        const __half* src = Wl + ch * 16384;
        #pragma unroll
        for (int i = 0; i < 4; ++i) {
            int idx = i * THREADS + tid;      // 2048 x 16B = 32 KB
            cpa16(b16 + idx * 16, src + idx * 8);
        }
        CP_COMMIT();
    };

    // ---- convert one chunk: A32 smem -> A16 swizzled tile ----
    auto cvt_stage = [&](int ch) {
        const uint32_t src = sA32 + (ch & 1) * A32_SZ;
        const uint32_t dst = sA16 + (ch & 1) * A16_SZ;
        #pragma unroll
        for (int i = 0; i < 4; ++i) {
            int idx = i * THREADS + tid;      // 2048 float4
            int r  = idx >> 4;
            int k4 = (idx & 15) * 4;
            float4 v;
            lds128(src + idx * 16, v);
            uint32_t off = swz(r, k4 >> 3) + ((k4 & 7) << 1);
            sts64(dst + off, cvt2(v.x, v.y), cvt2(v.z, v.w));
        }
    };

    // ---- consume one chunk: 4 k16 steps ----
    auto consume = [&](int ch) {
        const uint32_t sa = sA16 + (ch & 1) * A16_SZ;
        const uint32_t sw = sB16 + (ch % 3) * B_SZ;
        #pragma unroll
        for (int ks = 0; ks < 4; ++ks) {
            uint32_t ah[4][4];
            #pragma unroll
            for (int f = 0; f < 4; ++f) {
                int r = m0 + f * 16 + (lid & 15);
                int c = ks * 2 + (lid >> 4);
                LDSM4(ah[f][0], ah[f][1], ah[f][2], ah[f][3], sa + swz(r, c));
            }
            uint32_t bh[4][2];
            #pragma unroll
            for (int g2 = 0; g2 < 2; ++g2) {
                int r = n0 + g2 * 16 + (lid & 7) + ((lid >> 4) << 3);
                int c = ks * 2 + ((lid >> 3) & 1);
                LDSM4(bh[2 * g2][0], bh[2 * g2][1],
                      bh[2 * g2 + 1][0], bh[2 * g2 + 1][1], sw + swz(r, c));
            }
            #pragma unroll
            for (int f = 0; f < 4; ++f)
                #pragma unroll
                for (int g = 0; g < 4; ++g)
                    mma_f16(acc[f][g], ah[f], bh[g]);
        }
    };

    // ---- prologue: 2 chunks in flight, convert chunk 0 ----
    issue(0);
    issue(1);
    CP_WAIT(1);            // chunk 0 arrived
    __syncthreads();
    cvt_stage(0);

    // ---- main loop ----
    #pragma unroll
    for (int c = 0; c < NCHUNK; ++c) {
        CP_WAIT(0);        // chunk c+1 arrived (the only pending group)
        __syncthreads();   // cvt(c) + consume(c-1) complete everywhere
        if (c + 2 < NCHUNK) issue(c + 2);        // overlaps consume(c)
        if (c + 1 < NCHUNK) cvt_stage(c + 1);    // smem->smem, latency-tolerant
        consume(c);
    }

    // ---------------- epilogue ----------------
    const int tr = lid >> 2;          // 0..7
    const int tc = (lid & 3) * 2;     // 0,2,4,6
    #pragma unroll
    for (int f = 0; f < 4; ++f) {
        #pragma unroll
        for (int g = 0; g < 4; ++g) {
            int row = m0 + f * 16 + tr;
            int col = n0 + g * 8 + tc;
            float* p0 = Ob + (size_t)row * PD + col;
            *(float2*)p0            = make_float2(acc[f][g][0], acc[f][g][1]);
            *(float2*)(p0 + 8 * PD) = make_float2(acc[f][g][2], acc[f][g][3]);
        }
    }
}

extern "C" void kernel_launch(void* const* d_in, const int* in_sizes, int n_in,
                              void* d_out, int out_size) {
    const float* X    = (const float*)d_in[0];   // right_emb (B,S,D) f32
    const float* Wmap = (const float*)d_in[1];   // mapping (L,D,D) f32
    const int*   pid  = (const int*)d_in[2];     // pair_id (B,1) i32

    cvtW_kernel<<<512, 256>>>(Wmap);

    cudaFuncSetAttribute(mm_f16p_kernel,
                         cudaFuncAttributeMaxDynamicSharedMemorySize, SMEM_BYTES);
    dim3 grid(PS / TM, 1, PB);   // (32, 1, 64) = 2048 CTAs
    mm_f16p_kernel<<<grid, THREADS, SMEM_BYTES>>>(X, pid, (float*)d_out);
}

// round 11
// speedup vs baseline: 1.0323x; 1.0154x over previous
#include <cuda_runtime.h>
#include <cuda_fp16.h>
#include <cstdint>

#define PB 64
#define PS 4096
#define PD 256
#define PL 16

#define TM 128
#define TN 128
#define KC 64
#define NCHUNK (PD / KC)   // 4
#define THREADS 256

// per-stage tiles: A 128 rows x 128B, B 128 rows x 128B (fp16)
#define A_SZ (128 * 128)                 // 16384
#define B_SZ (128 * 128)                 // 16384
#define STAGE (A_SZ + B_SZ)              // 32768
#define SMEM_BYTES (2 * STAGE)           // 65536 -> 2 CTAs/SM fits (128KB/SM)

// Pre-converted, pre-swizzled fp16 W: [lang][chunk][row 0..255][64 halfs (swizzled 16B units)]
__device__ __align__(16) __half W16g[PL * PD * PD];

__device__ __forceinline__ uint32_t smem_u32(const void* p) {
    uint32_t a;
    asm("{ .reg .u64 t; cvta.to.shared.u64 t, %1; cvt.u32.u64 %0, t; }"
        : "=r"(a) : "l"(p));
    return a;
}

#define LDSM4(R0, R1, R2, R3, A)                                             \
    asm volatile("ldmatrix.sync.aligned.m8n8.x4.shared.b16 {%0,%1,%2,%3}, [%4];" \
                 : "=r"(R0), "=r"(R1), "=r"(R2), "=r"(R3) : "r"(A))

__device__ __forceinline__ void mma_f16(float* d, const uint32_t* a,
                                        const uint32_t* b) {
    asm volatile(
        "mma.sync.aligned.m16n8k16.row.col.f32.f16.f16.f32 "
        "{%0,%1,%2,%3}, {%4,%5,%6,%7}, {%8,%9}, {%0,%1,%2,%3};"
        : "+f"(d[0]), "+f"(d[1]), "+f"(d[2]), "+f"(d[3])
        : "r"(a[0]), "r"(a[1]), "r"(a[2]), "r"(a[3]), "r"(b[0]), "r"(b[1]));
}

__device__ __forceinline__ void sts64(uint32_t addr, uint32_t a, uint32_t b) {
    asm volatile("st.shared.v2.b32 [%0], {%1, %2};" :: "r"(addr), "r"(a), "r"(b));
}

__device__ __forceinline__ void cpa16(uint32_t dst, const void* gsrc) {
    asm volatile("cp.async.cg.shared.global [%0], [%1], 16;"
                 :: "r"(dst), "l"(gsrc));
}
#define CP_COMMIT() asm volatile("cp.async.commit_group;" ::: "memory")
#define CP_WAIT0()  asm volatile("cp.async.wait_group 0;" ::: "memory")

// swizzled byte offset for (row, 16B-chunk c) in a 128B-row tile
__device__ __forceinline__ uint32_t swz(int row, int c) {
    return (uint32_t)(row * 128 + (((c ^ (row & 7)) << 4)));
}

__device__ __forceinline__ uint32_t cvt2(float a, float b) {
    __half2 h = __floats2half2_rn(a, b);
    return *reinterpret_cast<uint32_t*>(&h);
}

// ---------------- pre-pass: W fp32 -> fp16, pre-swizzled tile layout ----------------
__global__ void cvtW_kernel(const float* __restrict__ W) {
    int idx = blockIdx.x * 256 + threadIdx.x;     // 0 .. 131071 (16B groups)
    int lang = idx >> 13;
    int rem = idx & 8191;
    int chunk = rem >> 11;
    int rem2 = rem & 2047;
    int r = rem2 >> 3;
    int g = rem2 & 7;
    const float* src = W + (((size_t)lang * PD + r) * PD + chunk * KC + g * 8);
    float4 v0 = ((const float4*)src)[0];
    float4 v1 = ((const float4*)src)[1];
    uint4 o;
    o.x = cvt2(v0.x, v0.y);
    o.y = cvt2(v0.z, v0.w);
    o.z = cvt2(v1.x, v1.y);
    o.w = cvt2(v1.z, v1.w);
    int gs = g ^ (r & 7);
    *(uint4*)(W16g + (size_t)lang * 65536 + chunk * 16384 + r * 64 + gs * 8) = o;
}

// ---------------- main GEMM ----------------
__global__ __launch_bounds__(THREADS, 2)
void mm_f16c_kernel(const float* __restrict__ X,
                    const int* __restrict__ pid,
                    float* __restrict__ out) {
    extern __shared__ char smem[];
    const int b  = blockIdx.z;
    const int s0 = blockIdx.x * TM;
    const int e0 = blockIdx.y * TN;
    const int tid = threadIdx.x;
    const int wid = tid >> 5;
    const int lid = tid & 31;

    int lang = pid[b];
    const float* __restrict__ Xb = X   + ((size_t)b * PS + s0) * PD;
    float* __restrict__       Ob = out + ((size_t)b * PS + s0) * PD;

    // ---------------- passthrough ----------------
    if (lang < 0) {
        #pragma unroll 4
        for (int i = 0; i < 16; ++i) {
            int idx = i * THREADS + tid;     // 4096 float4 in 128x128 tile
            int r = idx >> 5;
            int c = idx & 31;
            ((float4*)(Ob + (size_t)r * PD + e0))[c] =
                ((const float4*)(Xb + (size_t)r * PD + e0))[c];
        }
        return;
    }
    if (lang >= PL) lang = PL - 1;
    // B rows for this CTA: global rows e0..e0+127 of each chunk tile
    const __half* __restrict__ Wl = W16g + (size_t)lang * 65536 + (size_t)e0 * 64;

    const uint32_t sb = smem_u32(smem);

    // warp layout: 2 (M) x 4 (N); warp tile 64 x 32
    const int m0 = (wid & 1) * 64;
    const int n0 = (wid >> 1) * 32;

    float acc[4][4][4];
    #pragma unroll
    for (int f = 0; f < 4; ++f)
        #pragma unroll
        for (int g = 0; g < 4; ++g)
            #pragma unroll
            for (int q = 0; q < 4; ++q) acc[f][g][q] = 0.f;

    // ---- B: async copy one chunk (pre-swizzled fp16, linear 16KB block) ----
    auto issueB = [&](int ch, int stg) {
        const uint32_t swb = sb + stg * STAGE + A_SZ;
        const __half* src = Wl + ch * 16384;
        #pragma unroll
        for (int i = 0; i < 4; ++i) {
            int idx = i * THREADS + tid;      // 1024 x 16B = 16 KB
            cpa16(swb + idx * 16, src + idx * 8);
        }
        CP_COMMIT();
    };

    // ---- A: load fp32, convert, store swizzled ----
    auto produceA = [&](int kb, int stg) {
        const uint32_t sa = sb + stg * STAGE;
        #pragma unroll
        for (int i = 0; i < 8; ++i) {
            int idx = i * THREADS + tid;      // 2048 float4 (A: 128 rows x 64 k)
            int r  = idx >> 4;
            int k4 = (idx & 15) * 4;
            float4 v = *(const float4*)(Xb + (size_t)r * PD + kb + k4);
            uint32_t off = swz(r, k4 >> 3) + ((k4 & 7) << 1);
            sts64(sa + off, cvt2(v.x, v.y), cvt2(v.z, v.w));
        }
    };

    // ---- consume one stage: 4 k16 steps ----
    auto consume = [&](int stg) {
        const uint32_t sa = sb + stg * STAGE;
        const uint32_t sw = sa + A_SZ;
        #pragma unroll
        for (int ks = 0; ks < 4; ++ks) {
            uint32_t ah[4][4];
            #pragma unroll
            for (int f = 0; f < 4; ++f) {
                int r = m0 + f * 16 + (lid & 15);
                int c = ks * 2 + (lid >> 4);
                LDSM4(ah[f][0], ah[f][1], ah[f][2], ah[f][3], sa + swz(r, c));
            }
            uint32_t bh[4][2];
            #pragma unroll
            for (int g2 = 0; g2 < 2; ++g2) {
                int r = n0 + g2 * 16 + (lid & 7) + ((lid >> 4) << 3);
                int c = ks * 2 + ((lid >> 3) & 1);
                LDSM4(bh[2 * g2][0], bh[2 * g2][1],
                      bh[2 * g2 + 1][0], bh[2 * g2 + 1][1], sw + swz(r, c));
            }
            #pragma unroll
            for (int f = 0; f < 4; ++f)
                #pragma unroll
                for (int g = 0; g < 4; ++g)
                    mma_f16(acc[f][g], ah[f], bh[g]);
        }
    };

    // prologue
    issueB(0, 0);
    produceA(0, 0);
    CP_WAIT0();
    __syncthreads();

    #pragma unroll
    for (int c = 0; c < NCHUNK; ++c) {
        if (c + 1 < NCHUNK) {
            issueB(c + 1, (c + 1) & 1);       // async, overlaps consume
            produceA((c + 1) * KC, (c + 1) & 1);
        }
        consume(c & 1);
        if (c + 1 < NCHUNK) {
            CP_WAIT0();
            __syncthreads();
        }
    }

    // ---------------- epilogue ----------------
    const int tr = lid >> 2;          // 0..7
    const int tc = (lid & 3) * 2;     // 0,2,4,6
    #pragma unroll
    for (int f = 0; f < 4; ++f) {
        #pragma unroll
        for (int g = 0; g < 4; ++g) {
            int row = m0 + f * 16 + tr;
            int col = e0 + n0 + g * 8 + tc;
            float* p0 = Ob + (size_t)row * PD + col;
            *(float2*)p0            = make_float2(acc[f][g][0], acc[f][g][1]);
            *(float2*)(p0 + 8 * PD) = make_float2(acc[f][g][2], acc[f][g][3]);
        }
    }
}

extern "C" void kernel_launch(void* const* d_in, const int* in_sizes, int n_in,
                              void* d_out, int out_size) {
    const float* X    = (const float*)d_in[0];   // right_emb (B,S,D) f32
    const float* Wmap = (const float*)d_in[1];   // mapping (L,D,D) f32
    const int*   pid  = (const int*)d_in[2];     // pair_id (B,1) i32

    cvtW_kernel<<<512, 256>>>(Wmap);

    cudaFuncSetAttribute(mm_f16c_kernel,
                         cudaFuncAttributeMaxDynamicSharedMemorySize, SMEM_BYTES);
    dim3 grid(PS / TM, PD / TN, PB);   // (32, 2, 64) = 4096 CTAs
    mm_f16c_kernel<<<grid, THREADS, SMEM_BYTES>>>(X, pid, (float*)d_out);
}